// round 9
// baseline (speedup 1.0000x reference)
#include <cuda_runtime.h>
#include <cuda_bf16.h>
#include <cstdint>

// Problem constants
#define BB      8
#define NMAX    8192
#define CD      384
#define GGRP    512
#define KP      32
#define HH      6
#define DHD     64
#define PTS     (BB * NMAX)        // 65536 points
#define BGROUPS (BB * GGRP)        // 4096 groups
#define NROWS   (BGROUPS * KP)     // 131072 gathered rows
#define C3      (3 * CD)           // 1152

#define GEMM_LD      40            // padded bf16 smem stride
#define GEMM_STAGES  4
#define GEMM_STAGE_ELEMS (128 * GEMM_LD)
#define GEMM_SMEM_BYTES (2 * GEMM_STAGES * GEMM_STAGE_ELEMS * 2)  // A+B, bf16 = 81920 B

// ---------------- scratch (static __device__, no allocation) ----------------
__device__ __nv_bfloat16 g_feats[PTS * CD];                 // 50 MB
__device__ __nv_bfloat16 g_wqkv[C3 * CD];                   // 0.9 MB
__device__ __nv_bfloat16 g_wproj[CD * CD];                  // 0.3 MB
__device__ __nv_bfloat16 g_qkv[(size_t)PTS * C3];           // 151 MB
__device__ __nv_bfloat16 g_attnout[(size_t)NROWS * CD];     // 100 MB (masked rows stay 0)
__device__ float         g_acc[(size_t)PTS * CD];           // 100 MB
__device__ float         g_cnt[PTS];
__device__ int           g_rowSrc[NROWS];                   // gather row (b*N + idx)
__device__ int           g_rowTgt[NROWS];                   // scatter row, -1 if masked

// ---------------- helpers ----------------
__device__ __forceinline__ void cp16(void* smem_ptr, const void* gptr) {
    uint32_t s = (uint32_t)__cvta_generic_to_shared(smem_ptr);
    asm volatile("cp.async.cg.shared.global [%0], [%1], 16;\n" :: "r"(s), "l"(gptr));
}

// vectorized f32x2 global reduction (sm_90+), predicated
__device__ __forceinline__ void red_add_v2(float* gptr, float a, float b, bool pred) {
    asm volatile(
        "{\n\t"
        ".reg .pred p;\n\t"
        "setp.ne.u32 p, %3, 0;\n\t"
        "@p red.global.add.v2.f32 [%0], {%1, %2};\n\t"
        "}"
        :: "l"(gptr), "f"(a), "f"(b), "r"((unsigned)pred)
        : "memory");
}

#define MMA_BF16(d0,d1,d2,d3,a0,a1,a2,a3,b0,b1)                                  \
    asm volatile("mma.sync.aligned.m16n8k16.row.col.f32.bf16.bf16.f32 "          \
        "{%0,%1,%2,%3}, {%4,%5,%6,%7}, {%8,%9}, {%0,%1,%2,%3};\n"                \
        : "+f"(d0), "+f"(d1), "+f"(d2), "+f"(d3)                                 \
        : "r"(a0), "r"(a1), "r"(a2), "r"(a3), "r"(b0), "r"(b1))

// ---------------- kernel 0: fused zero + f32->bf16 conversions (1 launch) ----
__global__ void k_prep_data(const float* __restrict__ feats,
                            const float* __restrict__ wqkv,
                            const float* __restrict__ wproj) {
    const size_t i = (size_t)blockIdx.x * blockDim.x + threadIdx.x;
    const size_t stride = (size_t)gridDim.x * blockDim.x;

    // zero g_acc + g_cnt
    {
        float4 z = make_float4(0.f, 0.f, 0.f, 0.f);
        float4* a4 = reinterpret_cast<float4*>(g_acc);
        for (size_t j = i; j < (size_t)PTS * CD / 4; j += stride) a4[j] = z;
        float4* c4 = reinterpret_cast<float4*>(g_cnt);
        for (size_t j = i; j < PTS / 4; j += stride) c4[j] = z;
    }
    // feats -> bf16
    {
        const float4* s4 = reinterpret_cast<const float4*>(feats);
        __nv_bfloat162* d2 = reinterpret_cast<__nv_bfloat162*>(g_feats);
        for (size_t j = i; j < (size_t)PTS * CD / 4; j += stride) {
            float4 v = s4[j];
            d2[2 * j]     = __floats2bfloat162_rn(v.x, v.y);
            d2[2 * j + 1] = __floats2bfloat162_rn(v.z, v.w);
        }
    }
    // wqkv -> bf16
    {
        const float4* s4 = reinterpret_cast<const float4*>(wqkv);
        __nv_bfloat162* d2 = reinterpret_cast<__nv_bfloat162*>(g_wqkv);
        for (size_t j = i; j < (size_t)C3 * CD / 4; j += stride) {
            float4 v = s4[j];
            d2[2 * j]     = __floats2bfloat162_rn(v.x, v.y);
            d2[2 * j + 1] = __floats2bfloat162_rn(v.z, v.w);
        }
    }
    // wproj -> bf16
    {
        const float4* s4 = reinterpret_cast<const float4*>(wproj);
        __nv_bfloat162* d2 = reinterpret_cast<__nv_bfloat162*>(g_wproj);
        for (size_t j = i; j < (size_t)CD * CD / 4; j += stride) {
            float4 v = s4[j];
            d2[2 * j]     = __floats2bfloat162_rn(v.x, v.y);
            d2[2 * j + 1] = __floats2bfloat162_rn(v.z, v.w);
        }
    }
}

// ---------------- kernel 1: index prep + counts (separate launch: g_cnt must
// be fully zeroed grid-wide before the atomic counts begin) ------------------
// NOTE: grouping_idx is int32 on device (JAX x64 disabled downgrades the
// requested int64 to int32). Reading it as int64 was the R7 illegal access.
__global__ void k_prep(const int* __restrict__ gidx, const float* __restrict__ gmask) {
    int i = blockIdx.x * blockDim.x + threadIdx.x;
    if (i >= NROWS) return;
    int b = i >> 14;                         // / (512*32)
    int p = gidx[i];
    int pc = (p < 0) ? 0 : p;
    int row = (b << 13) + pc;                // b*NMAX + idx
    g_rowSrc[i] = row;
    float m = gmask[i];
    bool valid = (m > 0.f);
    g_rowTgt[i] = valid ? row : -1;
    if (valid) atomicAdd(&g_cnt[row], 1.0f);
}

// ---------------- GEMM: C[m,n] = sum_k A[m,k]*B[n,k]  (bf16 mma, f32 accum)
// Grid: x = N-tile (fast) -> A-tiles L2-resident across the N sweep.
// 4-stage cp.async ring (dynamic smem, 80 KB): 3 loads in flight cover
// ~577-cycle DRAM / ~250-cycle L2 latency behind ~320 cycles of HMMA per tile.
// MODE 0: A=g_feats (65536x384), B=g_wqkv (1152x384), store bf16 -> g_qkv
// MODE 1: A=g_attnout (131072x384), B=g_wproj (384x384), epilogue: +bias, masked red.v2 scatter
template <int MODE>
__launch_bounds__(256)
__global__ void k_gemm(const float* __restrict__ bias) {
    constexpr int LD = GEMM_LD;
    extern __shared__ __nv_bfloat16 smem[];
    __nv_bfloat16* sA = smem;                                     // [4][128*LD]
    __nv_bfloat16* sB = smem + GEMM_STAGES * GEMM_STAGE_ELEMS;    // [4][128*LD]

    const __nv_bfloat16* A  = (MODE == 0) ? g_feats : g_attnout;
    const __nv_bfloat16* Bw = (MODE == 0) ? g_wqkv : g_wproj;

    const int bm = blockIdx.y * 128;   // M-tile (slow)
    const int bn = blockIdx.x * 128;   // N-tile (fast) -> L2 reuse of A across N sweep
    const int tid = threadIdx.x;
    const int lane = tid & 31;
    const int warp = tid >> 5;
    const int wm = warp & 3;   // 4 warps along M (32 rows each)
    const int wn = warp >> 2;  // 2 warps along N (64 cols each)
    const int lg = lane >> 2;  // group id 0..7
    const int lt = lane & 3;   // thread-in-group

    float acc[2][8][4];
#pragma unroll
    for (int mt = 0; mt < 2; mt++)
#pragma unroll
        for (int nt = 0; nt < 8; nt++)
#pragma unroll
            for (int r = 0; r < 4; r++) acc[mt][nt][r] = 0.f;

    // tile loader: 512 16B chunks each for A and B, 256 threads -> 2 each
    auto load_tile = [&](int stage, int kt) {
        int k0 = kt * 32;
        __nv_bfloat16* dA = sA + stage * GEMM_STAGE_ELEMS;
        __nv_bfloat16* dB = sB + stage * GEMM_STAGE_ELEMS;
#pragma unroll
        for (int i = 0; i < 2; i++) {
            int c = tid + i * 256;
            int row = c >> 2, cc = c & 3;
            cp16(&dA[row * LD + cc * 8], A + (size_t)(bm + row) * CD + k0 + cc * 8);
            cp16(&dB[row * LD + cc * 8], Bw + (size_t)(bn + row) * CD + k0 + cc * 8);
        }
        asm volatile("cp.async.commit_group;\n" ::: "memory");
    };

    const int NK = CD / 32;  // 12
    load_tile(0, 0);
    load_tile(1, 1);
    load_tile(2, 2);

    for (int kt = 0; kt < NK; kt++) {
        if (kt + 3 < NK) {
            load_tile((kt + 3) & 3, kt + 3);
            asm volatile("cp.async.wait_group 3;\n" ::: "memory");
        } else {
            asm volatile("cp.async.wait_group 0;\n" ::: "memory");
        }
        __syncthreads();

        const __nv_bfloat16* pA = sA + (kt & 3) * GEMM_STAGE_ELEMS;
        const __nv_bfloat16* pB = sB + (kt & 3) * GEMM_STAGE_ELEMS;
#pragma unroll
        for (int step = 0; step < 2; step++) {
            int kk = step * 16 + lt * 2;
            uint32_t af[2][4], bf[8][2];
#pragma unroll
            for (int mt = 0; mt < 2; mt++) {
                int row = wm * 32 + mt * 16 + lg;
                const __nv_bfloat16* p = pA + row * LD + kk;
                af[mt][0] = *(const uint32_t*)(p);
                af[mt][1] = *(const uint32_t*)(p + 8 * LD);
                af[mt][2] = *(const uint32_t*)(p + 8);
                af[mt][3] = *(const uint32_t*)(p + 8 * LD + 8);
            }
#pragma unroll
            for (int nt = 0; nt < 8; nt++) {
                int cl = wn * 64 + nt * 8 + lg;
                const __nv_bfloat16* p = pB + cl * LD + kk;
                bf[nt][0] = *(const uint32_t*)(p);
                bf[nt][1] = *(const uint32_t*)(p + 8);
            }
#pragma unroll
            for (int mt = 0; mt < 2; mt++)
#pragma unroll
                for (int nt = 0; nt < 8; nt++)
                    MMA_BF16(acc[mt][nt][0], acc[mt][nt][1], acc[mt][nt][2], acc[mt][nt][3],
                             af[mt][0], af[mt][1], af[mt][2], af[mt][3], bf[nt][0], bf[nt][1]);
        }
        __syncthreads();
    }

    // epilogue
    if (MODE == 0) {
#pragma unroll
        for (int mt = 0; mt < 2; mt++) {
            int row = bm + wm * 32 + mt * 16 + lg;
#pragma unroll
            for (int nt = 0; nt < 8; nt++) {
                int col = bn + wn * 64 + nt * 8 + 2 * lt;
                *(__nv_bfloat162*)&g_qkv[(size_t)row * C3 + col] =
                    __floats2bfloat162_rn(acc[mt][nt][0], acc[mt][nt][1]);
                *(__nv_bfloat162*)&g_qkv[(size_t)(row + 8) * C3 + col] =
                    __floats2bfloat162_rn(acc[mt][nt][2], acc[mt][nt][3]);
            }
        }
    } else {
#pragma unroll
        for (int mt = 0; mt < 2; mt++) {
            int gr = bm + wm * 32 + mt * 16 + lg;
            int t0 = g_rowTgt[gr];
            int t1 = g_rowTgt[gr + 8];
#pragma unroll
            for (int nt = 0; nt < 8; nt++) {
                int col = bn + wn * 64 + nt * 8 + 2 * lt;
                float b0 = bias[col], b1 = bias[col + 1];
                red_add_v2(&g_acc[(size_t)(t0 < 0 ? 0 : t0) * CD + col],
                           acc[mt][nt][0] + b0, acc[mt][nt][1] + b1, t0 >= 0);
                red_add_v2(&g_acc[(size_t)(t1 < 0 ? 0 : t1) * CD + col],
                           acc[mt][nt][2] + b0, acc[mt][nt][3] + b1, t1 >= 0);
            }
        }
    }
}

// ---------------- kernel 3: per-(group, head) attention, one warp per block ----
// Q in registers (thread t owns query row t); only K,V staged in smem (17.4 KB).
// Invalid-query threads (mask=0) skip Q load, score/PV loops and the store:
// their g_attnout rows stay zero (never written since module load) and GEMM2's
// epilogue predicates them off, so they never reach the output.
__launch_bounds__(32, 12)
__global__ void k_attn() {
    __shared__ alignas(16) float Ks[32 * 68];     // pad 68: float4-aligned broadcast reads
    __shared__ alignas(16) float Vs[32 * 68];

    const int t = threadIdx.x;            // 0..31; also my query row
    const int gid = blockIdx.x;           // group 0..4095
    const int h = blockIdx.y;             // head 0..5

    const int myrow = g_rowSrc[gid * 32 + t];
    const int mytgt = g_rowTgt[gid * 32 + t];
    const unsigned vm = __ballot_sync(0xffffffffu, mytgt >= 0);  // valid-key bitmask

    // cooperative K,V gather: 32 rows x 64 dims, bf16 -> f32 smem (coalesced per row).
    // Unrolled so ptxas front-batches the independent LDGs (MLP ~16) to cover
    // the ~577-cycle DRAM gather latency.
#pragma unroll 8
    for (int r = 0; r < 32; r++) {
        int prow = __shfl_sync(0xffffffffu, myrow, r);
        const __nv_bfloat16* base = g_qkv + (size_t)prow * C3 + h * DHD;
        __nv_bfloat162 k = *(const __nv_bfloat162*)(base + CD + 2 * t);
        __nv_bfloat162 v = *(const __nv_bfloat162*)(base + 2 * CD + 2 * t);
        Ks[r * 68 + 2 * t]     = __low2float(k);
        Ks[r * 68 + 2 * t + 1] = __high2float(k);
        Vs[r * 68 + 2 * t]     = __low2float(v);
        Vs[r * 68 + 2 * t + 1] = __high2float(v);
    }
    __syncwarp();

    // ---- per-thread region below (no warp-collective ops): skip if masked query
    if (mytgt < 0) return;

    // own Q row: 64 dims = 128 contiguous bytes of bf16, 8x LDG.128 -> f32 regs
    const __nv_bfloat16* qbase = g_qkv + (size_t)myrow * C3 + h * DHD;
    float q[64];
#pragma unroll
    for (int i = 0; i < 8; i++) {
        uint4 u = *(const uint4*)(qbase + 8 * i);
        const __nv_bfloat162* b2 = reinterpret_cast<const __nv_bfloat162*>(&u);
#pragma unroll
        for (int j = 0; j < 4; j++) {
            float2 f = __bfloat1622float2(b2[j]);
            q[8 * i + 2 * j]     = f.x;
            q[8 * i + 2 * j + 1] = f.y;
        }
    }

    // scores: thread t computes its full query row (32 keys), K via smem broadcast
    float p[32];
#pragma unroll
    for (int k = 0; k < 32; k++) p[k] = 0.f;
#pragma unroll 4
    for (int d4 = 0; d4 < 16; d4++) {
        float q0 = q[4 * d4 + 0];
        float q1 = q[4 * d4 + 1];
        float q2 = q[4 * d4 + 2];
        float q3 = q[4 * d4 + 3];
#pragma unroll
        for (int k = 0; k < 32; k++) {
            float4 kv = *(const float4*)&Ks[k * 68 + 4 * d4];  // uniform -> broadcast
            p[k] += q0 * kv.x + q1 * kv.y + q2 * kv.z + q3 * kv.w;
        }
    }

    // softmax over keys (in registers)
    const float scale = 0.125f;  // 64^-0.5
    float m = -1e30f;
#pragma unroll
    for (int k = 0; k < 32; k++) {
        float s = p[k] * scale + (((vm >> k) & 1u) ? 0.f : -1e9f);
        p[k] = s;
        m = fmaxf(m, s);
    }
    float sum = 0.f;
#pragma unroll
    for (int k = 0; k < 32; k++) {
        float e = __expf(p[k] - m);
        p[k] = e;
        sum += e;
    }
    const float inv = 1.f / sum;

    // out[t][:] = sum_k p[k] * V[k][:] ; write directly (128B contiguous per thread)
    __nv_bfloat16* obase = g_attnout + (size_t)(gid * 32 + t) * CD + h * DHD;
#pragma unroll 4
    for (int d4 = 0; d4 < 16; d4 += 2) {
        float o[8];
#pragma unroll
        for (int j = 0; j < 8; j++) o[j] = 0.f;
#pragma unroll
        for (int k = 0; k < 32; k++) {
            float a = p[k];
            float4 v0 = *(const float4*)&Vs[k * 68 + 4 * d4];      // broadcast
            float4 v1 = *(const float4*)&Vs[k * 68 + 4 * d4 + 4];  // broadcast
            o[0] += a * v0.x; o[1] += a * v0.y; o[2] += a * v0.z; o[3] += a * v0.w;
            o[4] += a * v1.x; o[5] += a * v1.y; o[6] += a * v1.z; o[7] += a * v1.w;
        }
        uint4 st;
        __nv_bfloat162* s2 = reinterpret_cast<__nv_bfloat162*>(&st);
#pragma unroll
        for (int j = 0; j < 4; j++)
            s2[j] = __floats2bfloat162_rn(o[2 * j] * inv, o[2 * j + 1] * inv);
        *(uint4*)(obase + 4 * d4) = st;
    }
}

// ---------------- kernel 4: final combine ----------------
__global__ void k_final(const float* __restrict__ feats, const float* __restrict__ gamma,
                        float* __restrict__ out) {
    size_t i = (size_t)blockIdx.x * blockDim.x + threadIdx.x;
    size_t stride = (size_t)gridDim.x * blockDim.x;
    const float4* f4 = reinterpret_cast<const float4*>(feats);
    const float4* a4 = reinterpret_cast<const float4*>(g_acc);
    const float4* g4 = reinterpret_cast<const float4*>(gamma);
    float4* o4 = reinterpret_cast<float4*>(out);
    const size_t n4 = (size_t)PTS * CD / 4;
    for (size_t j = i; j < n4; j += stride) {
        float4 f = f4[j];
        float4 a = a4[j];
        int point = (int)(j / (CD / 4));
        int c4 = (int)(j % (CD / 4));
        float r = 1.f / fmaxf(g_cnt[point], 1.f);
        float4 g = g4[c4];
        f.x += a.x * r * g.x;
        f.y += a.y * r * g.y;
        f.z += a.z * r * g.z;
        f.w += a.w * r * g.w;
        o4[j] = f;
    }
}

// ---------------- launch ----------------
extern "C" void kernel_launch(void* const* d_in, const int* in_sizes, int n_in,
                              void* d_out, int out_size) {
    const float* feats = (const float*)d_in[0];
    const int*   gidx  = (const int*)d_in[1];   // int32 (JAX x64 disabled)
    const float* gmask = (const float*)d_in[2];
    const float* wqkv  = (const float*)d_in[3];
    const float* wproj = (const float*)d_in[4];
    const float* bproj = (const float*)d_in[5];
    const float* gamma = (const float*)d_in[6];
    float*       out   = (float*)d_out;

    // opt in to 80 KB dynamic smem (idempotent, capture-legal: enqueues nothing)
    cudaFuncSetAttribute(k_gemm<0>, cudaFuncAttributeMaxDynamicSharedMemorySize, GEMM_SMEM_BYTES);
    cudaFuncSetAttribute(k_gemm<1>, cudaFuncAttributeMaxDynamicSharedMemorySize, GEMM_SMEM_BYTES);

    k_prep_data<<<2048, 256>>>(feats, wqkv, wproj);             // zero + cvt (fused)
    k_prep<<<NROWS / 256, 256>>>(gidx, gmask);
    k_gemm<0><<<dim3(C3 / 128, PTS / 128), 256, GEMM_SMEM_BYTES>>>(nullptr);
    k_attn<<<dim3(BGROUPS, HH), 32>>>();                        // grouped attention
    k_gemm<1><<<dim3(CD / 128, NROWS / 128), 256, GEMM_SMEM_BYTES>>>(bproj);
    k_final<<<2048, 256>>>(feats, gamma, out);
}

// round 13
// speedup vs baseline: 1.3458x; 1.3458x over previous
#include <cuda_runtime.h>
#include <cuda_bf16.h>
#include <cstdint>

// Problem constants
#define BB      8
#define NMAX    8192
#define CD      384
#define GGRP    512
#define KP      32
#define HH      6
#define DHD     64
#define PTS     (BB * NMAX)        // 65536 points
#define BGROUPS (BB * GGRP)        // 4096 groups
#define NROWS   (BGROUPS * KP)     // 131072 gathered rows
#define C3      (3 * CD)           // 1152

#define GEMM_LD      40            // padded bf16 smem stride
#define GEMM_STAGES  4
#define GEMM_STAGE_ELEMS (128 * GEMM_LD)
#define GEMM_SMEM_BYTES (2 * GEMM_STAGES * GEMM_STAGE_ELEMS * 2)  // A+B, bf16 = 81920 B

#define ALD 72                     // k_attn smem row stride (bf16): conflict-free frags

// ---------------- scratch (static __device__, no allocation) ----------------
__device__ __nv_bfloat16 g_feats[PTS * CD];                 // 50 MB
__device__ __nv_bfloat16 g_wqkv[C3 * CD];                   // 0.9 MB
__device__ __nv_bfloat16 g_wproj[CD * CD];                  // 0.3 MB
__device__ __nv_bfloat16 g_qkv[(size_t)PTS * C3];           // 151 MB
__device__ __nv_bfloat16 g_attnout[(size_t)NROWS * CD];     // 100 MB
__device__ float         g_acc[(size_t)PTS * CD];           // 100 MB
__device__ float         g_cnt[PTS];
__device__ int           g_rowSrc[NROWS];                   // gather row (b*N + idx)
__device__ int           g_rowTgt[NROWS];                   // scatter row, -1 if masked

// ---------------- helpers ----------------
__device__ __forceinline__ void cp16(void* smem_ptr, const void* gptr) {
    uint32_t s = (uint32_t)__cvta_generic_to_shared(smem_ptr);
    asm volatile("cp.async.cg.shared.global [%0], [%1], 16;\n" :: "r"(s), "l"(gptr));
}

// vectorized f32x2 global reduction (sm_90+), predicated
__device__ __forceinline__ void red_add_v2(float* gptr, float a, float b, bool pred) {
    asm volatile(
        "{\n\t"
        ".reg .pred p;\n\t"
        "setp.ne.u32 p, %3, 0;\n\t"
        "@p red.global.add.v2.f32 [%0], {%1, %2};\n\t"
        "}"
        :: "l"(gptr), "f"(a), "f"(b), "r"((unsigned)pred)
        : "memory");
}

// pack two f32 -> bf16x2 (lo = first element, hi = second)
__device__ __forceinline__ uint32_t pk_bf2(float lo, float hi) {
    uint32_t r;
    asm("cvt.rn.bf16x2.f32 %0, %1, %2;" : "=r"(r) : "f"(hi), "f"(lo));
    return r;
}

#define MMA_BF16(d0,d1,d2,d3,a0,a1,a2,a3,b0,b1)                                  \
    asm volatile("mma.sync.aligned.m16n8k16.row.col.f32.bf16.bf16.f32 "          \
        "{%0,%1,%2,%3}, {%4,%5,%6,%7}, {%8,%9}, {%0,%1,%2,%3};\n"                \
        : "+f"(d0), "+f"(d1), "+f"(d2), "+f"(d3)                                 \
        : "r"(a0), "r"(a1), "r"(a2), "r"(a3), "r"(b0), "r"(b1))

// ---------------- kernel 0: fused zero + f32->bf16 conversions (1 launch) ----
__global__ void k_prep_data(const float* __restrict__ feats,
                            const float* __restrict__ wqkv,
                            const float* __restrict__ wproj) {
    const size_t i = (size_t)blockIdx.x * blockDim.x + threadIdx.x;
    const size_t stride = (size_t)gridDim.x * blockDim.x;

    {
        float4 z = make_float4(0.f, 0.f, 0.f, 0.f);
        float4* a4 = reinterpret_cast<float4*>(g_acc);
        for (size_t j = i; j < (size_t)PTS * CD / 4; j += stride) a4[j] = z;
        float4* c4 = reinterpret_cast<float4*>(g_cnt);
        for (size_t j = i; j < PTS / 4; j += stride) c4[j] = z;
    }
    {
        const float4* s4 = reinterpret_cast<const float4*>(feats);
        __nv_bfloat162* d2 = reinterpret_cast<__nv_bfloat162*>(g_feats);
        for (size_t j = i; j < (size_t)PTS * CD / 4; j += stride) {
            float4 v = s4[j];
            d2[2 * j]     = __floats2bfloat162_rn(v.x, v.y);
            d2[2 * j + 1] = __floats2bfloat162_rn(v.z, v.w);
        }
    }
    {
        const float4* s4 = reinterpret_cast<const float4*>(wqkv);
        __nv_bfloat162* d2 = reinterpret_cast<__nv_bfloat162*>(g_wqkv);
        for (size_t j = i; j < (size_t)C3 * CD / 4; j += stride) {
            float4 v = s4[j];
            d2[2 * j]     = __floats2bfloat162_rn(v.x, v.y);
            d2[2 * j + 1] = __floats2bfloat162_rn(v.z, v.w);
        }
    }
    {
        const float4* s4 = reinterpret_cast<const float4*>(wproj);
        __nv_bfloat162* d2 = reinterpret_cast<__nv_bfloat162*>(g_wproj);
        for (size_t j = i; j < (size_t)CD * CD / 4; j += stride) {
            float4 v = s4[j];
            d2[2 * j]     = __floats2bfloat162_rn(v.x, v.y);
            d2[2 * j + 1] = __floats2bfloat162_rn(v.z, v.w);
        }
    }
}

// ---------------- kernel 1: index prep + counts ----------------
// grouping_idx is int32 on device (JAX x64 disabled).
__global__ void k_prep(const int* __restrict__ gidx, const float* __restrict__ gmask) {
    int i = blockIdx.x * blockDim.x + threadIdx.x;
    if (i >= NROWS) return;
    int b = i >> 14;
    int p = gidx[i];
    int pc = (p < 0) ? 0 : p;
    int row = (b << 13) + pc;
    g_rowSrc[i] = row;
    float m = gmask[i];
    bool valid = (m > 0.f);
    g_rowTgt[i] = valid ? row : -1;
    if (valid) atomicAdd(&g_cnt[row], 1.0f);
}

// ---------------- GEMM (unchanged from R9-passing version) ----------------
template <int MODE>
__launch_bounds__(256)
__global__ void k_gemm(const float* __restrict__ bias) {
    constexpr int LD = GEMM_LD;
    extern __shared__ __nv_bfloat16 smem[];
    __nv_bfloat16* sA = smem;
    __nv_bfloat16* sB = smem + GEMM_STAGES * GEMM_STAGE_ELEMS;

    const __nv_bfloat16* A  = (MODE == 0) ? g_feats : g_attnout;
    const __nv_bfloat16* Bw = (MODE == 0) ? g_wqkv : g_wproj;

    const int bm = blockIdx.y * 128;
    const int bn = blockIdx.x * 128;
    const int tid = threadIdx.x;
    const int lane = tid & 31;
    const int warp = tid >> 5;
    const int wm = warp & 3;
    const int wn = warp >> 2;
    const int lg = lane >> 2;
    const int lt = lane & 3;

    float acc[2][8][4];
#pragma unroll
    for (int mt = 0; mt < 2; mt++)
#pragma unroll
        for (int nt = 0; nt < 8; nt++)
#pragma unroll
            for (int r = 0; r < 4; r++) acc[mt][nt][r] = 0.f;

    auto load_tile = [&](int stage, int kt) {
        int k0 = kt * 32;
        __nv_bfloat16* dA = sA + stage * GEMM_STAGE_ELEMS;
        __nv_bfloat16* dB = sB + stage * GEMM_STAGE_ELEMS;
#pragma unroll
        for (int i = 0; i < 2; i++) {
            int c = tid + i * 256;
            int row = c >> 2, cc = c & 3;
            cp16(&dA[row * LD + cc * 8], A + (size_t)(bm + row) * CD + k0 + cc * 8);
            cp16(&dB[row * LD + cc * 8], Bw + (size_t)(bn + row) * CD + k0 + cc * 8);
        }
        asm volatile("cp.async.commit_group;\n" ::: "memory");
    };

    const int NK = CD / 32;  // 12
    load_tile(0, 0);
    load_tile(1, 1);
    load_tile(2, 2);

    for (int kt = 0; kt < NK; kt++) {
        if (kt + 3 < NK) {
            load_tile((kt + 3) & 3, kt + 3);
            asm volatile("cp.async.wait_group 3;\n" ::: "memory");
        } else {
            asm volatile("cp.async.wait_group 0;\n" ::: "memory");
        }
        __syncthreads();

        const __nv_bfloat16* pA = sA + (kt & 3) * GEMM_STAGE_ELEMS;
        const __nv_bfloat16* pB = sB + (kt & 3) * GEMM_STAGE_ELEMS;
#pragma unroll
        for (int step = 0; step < 2; step++) {
            int kk = step * 16 + lt * 2;
            uint32_t af[2][4], bf[8][2];
#pragma unroll
            for (int mt = 0; mt < 2; mt++) {
                int row = wm * 32 + mt * 16 + lg;
                const __nv_bfloat16* p = pA + row * LD + kk;
                af[mt][0] = *(const uint32_t*)(p);
                af[mt][1] = *(const uint32_t*)(p + 8 * LD);
                af[mt][2] = *(const uint32_t*)(p + 8);
                af[mt][3] = *(const uint32_t*)(p + 8 * LD + 8);
            }
#pragma unroll
            for (int nt = 0; nt < 8; nt++) {
                int cl = wn * 64 + nt * 8 + lg;
                const __nv_bfloat16* p = pB + cl * LD + kk;
                bf[nt][0] = *(const uint32_t*)(p);
                bf[nt][1] = *(const uint32_t*)(p + 8);
            }
#pragma unroll
            for (int mt = 0; mt < 2; mt++)
#pragma unroll
                for (int nt = 0; nt < 8; nt++)
                    MMA_BF16(acc[mt][nt][0], acc[mt][nt][1], acc[mt][nt][2], acc[mt][nt][3],
                             af[mt][0], af[mt][1], af[mt][2], af[mt][3], bf[nt][0], bf[nt][1]);
        }
        __syncthreads();
    }

    if (MODE == 0) {
#pragma unroll
        for (int mt = 0; mt < 2; mt++) {
            int row = bm + wm * 32 + mt * 16 + lg;
#pragma unroll
            for (int nt = 0; nt < 8; nt++) {
                int col = bn + wn * 64 + nt * 8 + 2 * lt;
                *(__nv_bfloat162*)&g_qkv[(size_t)row * C3 + col] =
                    __floats2bfloat162_rn(acc[mt][nt][0], acc[mt][nt][1]);
                *(__nv_bfloat162*)&g_qkv[(size_t)(row + 8) * C3 + col] =
                    __floats2bfloat162_rn(acc[mt][nt][2], acc[mt][nt][3]);
            }
        }
    } else {
#pragma unroll
        for (int mt = 0; mt < 2; mt++) {
            int gr = bm + wm * 32 + mt * 16 + lg;
            int t0 = g_rowTgt[gr];
            int t1 = g_rowTgt[gr + 8];
#pragma unroll
            for (int nt = 0; nt < 8; nt++) {
                int col = bn + wn * 64 + nt * 8 + 2 * lt;
                float b0 = bias[col], b1 = bias[col + 1];
                red_add_v2(&g_acc[(size_t)(t0 < 0 ? 0 : t0) * CD + col],
                           acc[mt][nt][0] + b0, acc[mt][nt][1] + b1, t0 >= 0);
                red_add_v2(&g_acc[(size_t)(t1 < 0 ? 0 : t1) * CD + col],
                           acc[mt][nt][2] + b0, acc[mt][nt][3] + b1, t1 >= 0);
            }
        }
    }
}

// ---------------- kernel 3: tensor-core attention, one warp per (group, head) ----
// S = Q K^T via mma.m16n8k16 (same frag pattern as the validated k_gemm),
// softmax in C-fragment layout (quad shfl.bfly row reductions), P reused as
// the PV A-operand via the C->A layout identity, 1/l applied at the store.
__launch_bounds__(32, 16)
__global__ void k_attn() {
    __shared__ __nv_bfloat16 Qs[32 * ALD];   // [row][dim], pad 72: conflict-free
    __shared__ __nv_bfloat16 Ks[32 * ALD];   // [key][dim]
    __shared__ __nv_bfloat16 Vs[32 * ALD];   // [key][dim]

    const int t = threadIdx.x;
    const int gid = blockIdx.x;
    const int h = blockIdx.y;

    const int myrow = g_rowSrc[gid * 32 + t];
    const int mytgt = g_rowTgt[gid * 32 + t];
    const unsigned vm = __ballot_sync(0xffffffffu, mytgt >= 0);  // valid-key bits

    // gather Q,K,V rows into bf16 smem (coalesced 128B per row; STS conflict-free)
#pragma unroll 8
    for (int r = 0; r < 32; r++) {
        int prow = __shfl_sync(0xffffffffu, myrow, r);
        const __nv_bfloat16* base = g_qkv + (size_t)prow * C3 + h * DHD;
        uint32_t q2 = *(const uint32_t*)(base + 2 * t);
        uint32_t k2 = *(const uint32_t*)(base + CD + 2 * t);
        uint32_t v2 = *(const uint32_t*)(base + 2 * CD + 2 * t);
        *(uint32_t*)&Qs[r * ALD + 2 * t] = q2;
        *(uint32_t*)&Ks[r * ALD + 2 * t] = k2;
        *(uint32_t*)&Vs[r * ALD + 2 * t] = v2;
    }
    __syncwarp();

    const int g  = t >> 2;   // 0..7
    const int tq = t & 3;    // 0..3

    // ---- S = Q K^T : M=32 (2 tiles), N=32 keys (4 tiles), K=64 (4 steps)
    float sacc[2][4][4];
#pragma unroll
    for (int mi = 0; mi < 2; mi++)
#pragma unroll
        for (int ni = 0; ni < 4; ni++)
#pragma unroll
            for (int j = 0; j < 4; j++) sacc[mi][ni][j] = 0.f;

#pragma unroll
    for (int mi = 0; mi < 2; mi++) {
#pragma unroll
        for (int ks = 0; ks < 4; ks++) {
            uint32_t a0 = *(const uint32_t*)&Qs[(16 * mi + g) * ALD + 16 * ks + 2 * tq];
            uint32_t a1 = *(const uint32_t*)&Qs[(16 * mi + 8 + g) * ALD + 16 * ks + 2 * tq];
            uint32_t a2 = *(const uint32_t*)&Qs[(16 * mi + g) * ALD + 16 * ks + 8 + 2 * tq];
            uint32_t a3 = *(const uint32_t*)&Qs[(16 * mi + 8 + g) * ALD + 16 * ks + 8 + 2 * tq];
#pragma unroll
            for (int ni = 0; ni < 4; ni++) {
                uint32_t b0 = *(const uint32_t*)&Ks[(8 * ni + g) * ALD + 16 * ks + 2 * tq];
                uint32_t b1 = *(const uint32_t*)&Ks[(8 * ni + g) * ALD + 16 * ks + 8 + 2 * tq];
                MMA_BF16(sacc[mi][ni][0], sacc[mi][ni][1], sacc[mi][ni][2], sacc[mi][ni][3],
                         a0, a1, a2, a3, b0, b1);
            }
        }
    }

    // ---- scale + key-mask bias (element (j): col = 8*ni + 2*tq + (j&1))
    const float scale = 0.125f;  // 64^-0.5
#pragma unroll
    for (int mi = 0; mi < 2; mi++)
#pragma unroll
        for (int ni = 0; ni < 4; ni++)
#pragma unroll
            for (int j = 0; j < 4; j++) {
                int col = 8 * ni + 2 * tq + (j & 1);
                float bias = ((vm >> col) & 1u) ? 0.f : -1e9f;
                sacc[mi][ni][j] = sacc[mi][ni][j] * scale + bias;
            }

    // ---- softmax per row; rows per thread: (mi, half): row = 16*mi + 8*half + g
    float inv_[2][2];
#pragma unroll
    for (int mi = 0; mi < 2; mi++) {
#pragma unroll
        for (int hf = 0; hf < 2; hf++) {
            float mx = -1e30f;
#pragma unroll
            for (int ni = 0; ni < 4; ni++) {
                mx = fmaxf(mx, sacc[mi][ni][2 * hf]);
                mx = fmaxf(mx, sacc[mi][ni][2 * hf + 1]);
            }
            mx = fmaxf(mx, __shfl_xor_sync(0xffffffffu, mx, 1));
            mx = fmaxf(mx, __shfl_xor_sync(0xffffffffu, mx, 2));
            float sm = 0.f;
#pragma unroll
            for (int ni = 0; ni < 4; ni++) {
#pragma unroll
                for (int jj = 0; jj < 2; jj++) {
                    float e = __expf(sacc[mi][ni][2 * hf + jj] - mx);
                    sacc[mi][ni][2 * hf + jj] = e;
                    sm += e;
                }
            }
            sm += __shfl_xor_sync(0xffffffffu, sm, 1);
            sm += __shfl_xor_sync(0xffffffffu, sm, 2);
            inv_[mi][hf] = 1.f / sm;
        }
    }

    // ---- pack P (unnormalized) into A-fragment regs via the C->A identity
    // pb[mi][ni][0] = rows g (c0,c1);  pb[mi][ni][1] = rows g+8 (c2,c3)
    uint32_t pb[2][4][2];
#pragma unroll
    for (int mi = 0; mi < 2; mi++)
#pragma unroll
        for (int ni = 0; ni < 4; ni++) {
            pb[mi][ni][0] = pk_bf2(sacc[mi][ni][0], sacc[mi][ni][1]);
            pb[mi][ni][1] = pk_bf2(sacc[mi][ni][2], sacc[mi][ni][3]);
        }

    // ---- O = P V : M=32, N=64 dims (8 tiles), K=32 keys (2 steps)
#pragma unroll
    for (int nj = 0; nj < 8; nj++) {
        float oa[2][4];
#pragma unroll
        for (int mi = 0; mi < 2; mi++)
#pragma unroll
            for (int j = 0; j < 4; j++) oa[mi][j] = 0.f;

#pragma unroll
        for (int ks = 0; ks < 2; ks++) {
            // B frag: element (k=key, n=dim): b0 = V[16ks+2tq(+1)][8nj+g]
            int dim = 8 * nj + g;
            int k0 = 16 * ks + 2 * tq;
            uint32_t b0 = (uint32_t)*(const unsigned short*)&Vs[k0 * ALD + dim]
                        | ((uint32_t)*(const unsigned short*)&Vs[(k0 + 1) * ALD + dim] << 16);
            uint32_t b1 = (uint32_t)*(const unsigned short*)&Vs[(k0 + 8) * ALD + dim]
                        | ((uint32_t)*(const unsigned short*)&Vs[(k0 + 9) * ALD + dim] << 16);
#pragma unroll
            for (int mi = 0; mi < 2; mi++) {
                MMA_BF16(oa[mi][0], oa[mi][1], oa[mi][2], oa[mi][3],
                         pb[mi][2 * ks][0], pb[mi][2 * ks][1],
                         pb[mi][2 * ks + 1][0], pb[mi][2 * ks + 1][1],
                         b0, b1);
            }
        }

        // store: rows 16mi+g (c0,c1) and 16mi+8+g (c2,c3); cols h*64+8nj+2tq(,+1)
#pragma unroll
        for (int mi = 0; mi < 2; mi++) {
            int row0 = gid * 32 + 16 * mi + g;
            int col = h * DHD + 8 * nj + 2 * tq;
            *(uint32_t*)&g_attnout[(size_t)row0 * CD + col] =
                pk_bf2(oa[mi][0] * inv_[mi][0], oa[mi][1] * inv_[mi][0]);
            *(uint32_t*)&g_attnout[(size_t)(row0 + 8) * CD + col] =
                pk_bf2(oa[mi][2] * inv_[mi][1], oa[mi][3] * inv_[mi][1]);
        }
    }
}

// ---------------- kernel 4: final combine ----------------
__global__ void k_final(const float* __restrict__ feats, const float* __restrict__ gamma,
                        float* __restrict__ out) {
    size_t i = (size_t)blockIdx.x * blockDim.x + threadIdx.x;
    size_t stride = (size_t)gridDim.x * blockDim.x;
    const float4* f4 = reinterpret_cast<const float4*>(feats);
    const float4* a4 = reinterpret_cast<const float4*>(g_acc);
    const float4* g4 = reinterpret_cast<const float4*>(gamma);
    float4* o4 = reinterpret_cast<float4*>(out);
    const size_t n4 = (size_t)PTS * CD / 4;
    for (size_t j = i; j < n4; j += stride) {
        float4 f = f4[j];
        float4 a = a4[j];
        int point = (int)(j / (CD / 4));
        int c4 = (int)(j % (CD / 4));
        float r = 1.f / fmaxf(g_cnt[point], 1.f);
        float4 g = g4[c4];
        f.x += a.x * r * g.x;
        f.y += a.y * r * g.y;
        f.z += a.z * r * g.z;
        f.w += a.w * r * g.w;
        o4[j] = f;
    }
}

// ---------------- launch ----------------
extern "C" void kernel_launch(void* const* d_in, const int* in_sizes, int n_in,
                              void* d_out, int out_size) {
    const float* feats = (const float*)d_in[0];
    const int*   gidx  = (const int*)d_in[1];   // int32 (JAX x64 disabled)
    const float* gmask = (const float*)d_in[2];
    const float* wqkv  = (const float*)d_in[3];
    const float* wproj = (const float*)d_in[4];
    const float* bproj = (const float*)d_in[5];
    const float* gamma = (const float*)d_in[6];
    float*       out   = (float*)d_out;

    cudaFuncSetAttribute(k_gemm<0>, cudaFuncAttributeMaxDynamicSharedMemorySize, GEMM_SMEM_BYTES);
    cudaFuncSetAttribute(k_gemm<1>, cudaFuncAttributeMaxDynamicSharedMemorySize, GEMM_SMEM_BYTES);

    k_prep_data<<<2048, 256>>>(feats, wqkv, wproj);
    k_prep<<<NROWS / 256, 256>>>(gidx, gmask);
    k_gemm<0><<<dim3(C3 / 128, PTS / 128), 256, GEMM_SMEM_BYTES>>>(nullptr);
    k_attn<<<dim3(BGROUPS, HH), 32>>>();
    k_gemm<1><<<dim3(CD / 128, NROWS / 128), 256, GEMM_SMEM_BYTES>>>(bproj);
    k_final<<<2048, 256>>>(feats, gamma, out);
}